// round 15
// baseline (speedup 1.0000x reference)
#include <cuda_runtime.h>
#include <math_constants.h>
#include <cstdint>

// Problem constants (fixed by the reference)
#define BB 16
#define LL 2048
#define DD 512
#define SPLIT 32       // 1024 CTAs, one wave
#define NGROUPS 8      // pipeline groups
#define RPG 2          // rows per group -> ring = 16 rows x 2KB = 32KB
#define ROWB (DD * 4)  // 2048 bytes per row

// Final max accumulators, monotone-u32 encoded. Zero == encoded(-inf).
// Zero-initialized at module load; the reducer CTA resets its batch slice
// after use, so every graph replay starts from identical state.
__device__ unsigned int g_max[2][BB][DD];
__device__ unsigned int g_count[BB];

// Streaming copy with L2 evict-first policy: the 64MB x/y stream passes L2
// exactly once, so mark it evict-first to keep masks/g_max/W resident and
// reduce L2 fill-management pressure.
#define CP_ASYNC16_EF(smem_u32, gptr, pol) \
    asm volatile("cp.async.cg.shared.global.L2::cache_hint [%0], [%1], 16, %2;\n" \
                 :: "r"(smem_u32), "l"(gptr), "l"(pol) : "memory")
#define CP_COMMIT() asm volatile("cp.async.commit_group;\n" ::: "memory")
#define CP_WAIT(n)  asm volatile("cp.async.wait_group %0;\n" :: "n"(n) : "memory")

// Order-preserving f32 -> u32 with encoded(-inf) == 0 (inputs are finite).
__device__ __forceinline__ unsigned int f2mono(float f) {
    unsigned int u = __float_as_uint(f);
    u = (u & 0x80000000u) ? ~u : (u | 0x80000000u);
    return u - 0x007FFFFFu;
}
__device__ __forceinline__ float mono2f(unsigned int m) {
    unsigned int u = m + 0x007FFFFFu;
    u = (u & 0x80000000u) ? (u & 0x7FFFFFFFu) : ~u;
    return __uint_as_float(u);
}

__device__ __forceinline__ void fmax4(float4& a, const float4 v) {
    a.x = fmaxf(a.x, v.x); a.y = fmaxf(a.y, v.y);
    a.z = fmaxf(a.z, v.z); a.w = fmaxf(a.w, v.w);
}

// Fused kernel: masked max, strided rows (CTA 'split' owns rows split+i*SPLIT;
// static addresses -> the 16-row cp.async prologue launches BEFORE len is known,
// hiding the mask reduction). 2 rows per commit group; wrap counters, no modulo.
// Streaming loads carry an L2 evict-first policy. Cross-CTA combine via red.max
// on monotone-encoded u32; last CTA per batch decodes + dots W + resets state.
// grid=(SPLIT,B,2), block=128 (thread t owns dims 4t..4t+3).
__global__ void __launch_bounds__(128, 7) fused_kernel(
    const float* __restrict__ x,
    const float* __restrict__ y,
    const int* __restrict__ mask_x,
    const int* __restrict__ mask_y,
    const float* __restrict__ W,
    const float* __restrict__ bias,
    float* __restrict__ out)
{
    __shared__ __align__(16) float buf[NGROUPS][RPG][DD];   // 32 KB ring
    __shared__ int   warp_sums[4];
    __shared__ int   s_last;
    __shared__ float red[4];

    const int split = blockIdx.x;
    const int b     = blockIdx.y;
    const int which = blockIdx.z;
    const int t     = threadIdx.x;   // 0..127

    const float* v = which ? y : x;
    const int*   m = which ? mask_y : mask_x;

    // evict-first L2 policy for the one-pass x/y stream
    uint64_t pol;
    asm volatile("createpolicy.fractional.L2::evict_first.b64 %0, 1.0;" : "=l"(pol));

    const float*   gbase = v + (size_t)b * LL * DD + 4 * t;  // this thread's 16B column
    const uint32_t smem0 = (uint32_t)__cvta_generic_to_shared(&buf[0][0][4 * t]);
    const size_t   gstep = (size_t)SPLIT * DD;               // one strided row

    // ---- prologue FIRST: groups p = strided rows (2p, 2p+1); indices <= 15 ->
    // sequence index split + 15*32 < LL, always in-bounds; rows beyond len are
    // fetched but never accumulated ----
    #pragma unroll
    for (int p = 0; p < NGROUPS; p++) {
        CP_ASYNC16_EF(smem0 + (uint32_t)(2 * p + 0) * ROWB,
                      gbase + (size_t)(split + (2 * p + 0) * SPLIT) * DD, pol);
        CP_ASYNC16_EF(smem0 + (uint32_t)(2 * p + 1) * ROWB,
                      gbase + (size_t)(split + (2 * p + 1) * SPLIT) * DD, pol);
        CP_COMMIT();
    }

    // ---- len[b] = L - sum(mask[b,:]) — overlapped with in-flight loads ----
    int sum = 0;
    const int4* mrow = reinterpret_cast<const int4*>(m + (size_t)b * LL);
    #pragma unroll
    for (int i = t; i < LL / 4; i += 128) {
        int4 mv = mrow[i];
        sum += mv.x + mv.y + mv.z + mv.w;
    }
    sum = __reduce_add_sync(0xffffffffu, sum);
    if ((t & 31) == 0) warp_sums[t >> 5] = sum;
    __syncthreads();
    const int len = LL - (warp_sums[0] + warp_sums[1] + warp_sums[2] + warp_sums[3]);

    // valid strided rows: split + r*SPLIT < len
    const int n  = (len > split) ? ((len - split + SPLIT - 1) / SPLIT) : 0;   // <= 64
    const int np = (n + 1) >> 1;                                               // pairs

    float4 mx = make_float4(-CUDART_INF_F, -CUDART_INF_F, -CUDART_INF_F, -CUDART_INF_F);

    // ---- steady state over pairs: wrap counter, incremental pointers ----
    int st = 0;                                        // ring group to consume/refill
    uint32_t sm_rd = smem0;                            // smem addr of group st (this thread)
    const float* gnext = gbase + (size_t)(split + 2 * NGROUPS * SPLIT) * DD;  // next row to issue

    for (int j = 0; j < np; j++) {
        CP_WAIT(NGROUPS - 1);   // 1 group/iteration -> group j has landed

        fmax4(mx, *reinterpret_cast<const float4*>(&buf[st][0][4 * t]));
        if (2 * j + 1 < n)
            fmax4(mx, *reinterpret_cast<const float4*>(&buf[st][1][4 * t]));

        if (j + NGROUPS < np) {   // refill group st with the next row pair
            CP_ASYNC16_EF(sm_rd,        gnext,         pol);
            CP_ASYNC16_EF(sm_rd + ROWB, gnext + gstep, pol);
            gnext += 2 * gstep;
        }
        CP_COMMIT();

        sm_rd += RPG * ROWB;
        if (++st == NGROUPS) { st = 0; sm_rd = smem0; }
    }
    CP_WAIT(0);   // drain over-issued prologue groups

    // ---- merge into final accumulator via L2 red.max (no partial buffer) ----
    unsigned int* gm = &g_max[which][b][4 * t];
    atomicMax(gm + 0, f2mono(mx.x));
    atomicMax(gm + 1, f2mono(mx.y));
    atomicMax(gm + 2, f2mono(mx.z));
    atomicMax(gm + 3, f2mono(mx.w));

    // ---- last-arriving CTA for this batch: decode + dot + reset ----
    __threadfence();
    __syncthreads();

    if (t == 0) {
        unsigned int old = atomicAdd(&g_count[b], 1u);
        s_last = (old == 2u * SPLIT - 1u);
    }
    __syncthreads();
    if (!s_last) return;

    __threadfence();   // acquire: see all other CTAs' red.max results

    uint4 ux = *reinterpret_cast<const uint4*>(&g_max[0][b][4 * t]);
    uint4 uy = *reinterpret_cast<const uint4*>(&g_max[1][b][4 * t]);

    const float4* W4 = reinterpret_cast<const float4*>(W);
    float4 wx = W4[t];            // W[0:512]    -> x part
    float4 wy = W4[DD / 4 + t];   // W[512:1024] -> y part

    float val = wx.x * mono2f(ux.x) + wx.y * mono2f(ux.y)
              + wx.z * mono2f(ux.z) + wx.w * mono2f(ux.w)
              + wy.x * mono2f(uy.x) + wy.y * mono2f(uy.y)
              + wy.z * mono2f(uy.z) + wy.w * mono2f(uy.w);

    #pragma unroll
    for (int o = 16; o; o >>= 1) val += __shfl_down_sync(0xffffffffu, val, o);

    if ((t & 31) == 0) red[t >> 5] = val;

    // reset this batch's accumulators for the next replay
    const uint4 z = make_uint4(0, 0, 0, 0);
    *reinterpret_cast<uint4*>(&g_max[0][b][4 * t]) = z;
    *reinterpret_cast<uint4*>(&g_max[1][b][4 * t]) = z;

    __syncthreads();
    if (t == 0) {
        out[b] = red[0] + red[1] + red[2] + red[3] + bias[0];
        g_count[b] = 0;   // reset for the next graph replay
    }
}

extern "C" void kernel_launch(void* const* d_in, const int* in_sizes, int n_in,
                              void* d_out, int out_size)
{
    const float* x      = (const float*)d_in[0];
    const float* y      = (const float*)d_in[1];
    const int*   mask_x = (const int*)d_in[2];
    const int*   mask_y = (const int*)d_in[3];
    const float* W      = (const float*)d_in[4];
    const float* bias   = (const float*)d_in[5];
    float* out          = (float*)d_out;

    fused_kernel<<<dim3(SPLIT, BB, 2), 128>>>(x, y, mask_x, mask_y, W, bias, out);
}

// round 16
// speedup vs baseline: 1.3814x; 1.3814x over previous
#include <cuda_runtime.h>
#include <math_constants.h>
#include <cstdint>

// Problem constants (fixed by the reference)
#define BB 16
#define LL 2048
#define DD 512
#define SPLIT 32       // 1024 CTAs, one wave
#define NGROUPS 8      // pipeline groups
#define RPG 2          // rows per group -> ring = 16 rows x 2KB = 32KB
#define ROWB (DD * 4)  // 2048 bytes per row

// Final max accumulators, monotone-u32 encoded. Zero == encoded(-inf).
// Zero-initialized at module load; the reducer CTA resets its batch slice
// after use, so every graph replay starts from identical state.
__device__ unsigned int g_max[2][BB][DD];
__device__ unsigned int g_count[BB];

#define CP_ASYNC16(smem_u32, gptr) \
    asm volatile("cp.async.cg.shared.global [%0], [%1], 16;\n" :: "r"(smem_u32), "l"(gptr) : "memory")
#define CP_COMMIT() asm volatile("cp.async.commit_group;\n" ::: "memory")
#define CP_WAIT(n)  asm volatile("cp.async.wait_group %0;\n" :: "n"(n) : "memory")

// Order-preserving f32 -> u32 with encoded(-inf) == 0 (inputs are finite).
__device__ __forceinline__ unsigned int f2mono(float f) {
    unsigned int u = __float_as_uint(f);
    u = (u & 0x80000000u) ? ~u : (u | 0x80000000u);
    return u - 0x007FFFFFu;
}
__device__ __forceinline__ float mono2f(unsigned int m) {
    unsigned int u = m + 0x007FFFFFu;
    u = (u & 0x80000000u) ? (u & 0x7FFFFFFFu) : ~u;
    return __uint_as_float(u);
}

__device__ __forceinline__ void fmax4(float4& a, const float4 v) {
    a.x = fmaxf(a.x, v.x); a.y = fmaxf(a.y, v.y);
    a.z = fmaxf(a.z, v.z); a.w = fmaxf(a.w, v.w);
}

// acq_rel arrival: release publishes this CTA's prior g_max atomics; acquire
// (observed by the last arriver) orders its subsequent g_max reads. Replaces
// two device-wide __threadfence() per CTA.
__device__ __forceinline__ unsigned int arrive_acq_rel(unsigned int* p) {
    unsigned int old;
    asm volatile("atom.add.acq_rel.gpu.global.u32 %0, [%1], 1;"
                 : "=r"(old) : "l"(p) : "memory");
    return old;
}

// Fused kernel: masked max, strided rows (CTA 'split' owns rows split+i*SPLIT;
// static addresses -> the 16-row cp.async prologue launches BEFORE len is known,
// hiding the mask reduction). 2 rows per commit group; wrap counters, no modulo.
// Cross-CTA combine via red.max on monotone-encoded u32; last CTA per batch
// decodes + dots W + resets state. grid=(SPLIT,B,2), block=128.
__global__ void __launch_bounds__(128, 7) fused_kernel(
    const float* __restrict__ x,
    const float* __restrict__ y,
    const int* __restrict__ mask_x,
    const int* __restrict__ mask_y,
    const float* __restrict__ W,
    const float* __restrict__ bias,
    float* __restrict__ out)
{
    __shared__ __align__(16) float buf[NGROUPS][RPG][DD];   // 32 KB ring
    __shared__ int   warp_sums[4];
    __shared__ int   s_last;
    __shared__ float red[4];

    const int split = blockIdx.x;
    const int b     = blockIdx.y;
    const int which = blockIdx.z;
    const int t     = threadIdx.x;   // 0..127

    const float* v = which ? y : x;
    const int*   m = which ? mask_y : mask_x;

    const float*   gbase = v + (size_t)b * LL * DD + 4 * t;  // this thread's 16B column
    const uint32_t smem0 = (uint32_t)__cvta_generic_to_shared(&buf[0][0][4 * t]);
    const size_t   gstep = (size_t)SPLIT * DD;               // one strided row

    // ---- prologue FIRST: groups p = strided rows (2p, 2p+1); indices <= 15 ->
    // sequence index split + 15*32 < LL, always in-bounds; rows beyond len are
    // fetched but never accumulated ----
    #pragma unroll
    for (int p = 0; p < NGROUPS; p++) {
        CP_ASYNC16(smem0 + (uint32_t)(2 * p + 0) * ROWB, gbase + (size_t)(split + (2 * p + 0) * SPLIT) * DD);
        CP_ASYNC16(smem0 + (uint32_t)(2 * p + 1) * ROWB, gbase + (size_t)(split + (2 * p + 1) * SPLIT) * DD);
        CP_COMMIT();
    }

    // ---- len[b] = L - sum(mask[b,:]) — overlapped with in-flight loads ----
    int sum = 0;
    const int4* mrow = reinterpret_cast<const int4*>(m + (size_t)b * LL);
    #pragma unroll
    for (int i = t; i < LL / 4; i += 128) {
        int4 mv = mrow[i];
        sum += mv.x + mv.y + mv.z + mv.w;
    }
    sum = __reduce_add_sync(0xffffffffu, sum);
    if ((t & 31) == 0) warp_sums[t >> 5] = sum;
    __syncthreads();
    const int len = LL - (warp_sums[0] + warp_sums[1] + warp_sums[2] + warp_sums[3]);

    // valid strided rows: split + r*SPLIT < len
    const int n       = (len > split) ? ((len - split + SPLIT - 1) / SPLIT) : 0;  // <= 64
    const int np      = (n + 1) >> 1;   // total groups to wait on
    const int np_full = n >> 1;         // groups where BOTH rows are valid

    float4 mx = make_float4(-CUDART_INF_F, -CUDART_INF_F, -CUDART_INF_F, -CUDART_INF_F);

    // ---- steady state: full pairs, branch-free consume ----
    int st = 0;                                        // ring group to consume/refill
    uint32_t sm_rd = smem0;                            // smem addr of group st (this thread)
    const float* gnext = gbase + (size_t)(split + 2 * NGROUPS * SPLIT) * DD;  // next row to issue

    for (int j = 0; j < np_full; j++) {
        CP_WAIT(NGROUPS - 1);   // 1 group/iteration -> group j has landed

        fmax4(mx, *reinterpret_cast<const float4*>(&buf[st][0][4 * t]));
        fmax4(mx, *reinterpret_cast<const float4*>(&buf[st][1][4 * t]));

        if (j + NGROUPS < np) {   // refill group st with the next row pair
            CP_ASYNC16(sm_rd,        gnext);
            CP_ASYNC16(sm_rd + ROWB, gnext + gstep);
            gnext += 2 * gstep;
        }
        CP_COMMIT();

        sm_rd += RPG * ROWB;
        if (++st == NGROUPS) { st = 0; sm_rd = smem0; }
    }
    if (np > np_full) {   // odd trailing row (first row of the last group)
        CP_WAIT(NGROUPS - 1);
        fmax4(mx, *reinterpret_cast<const float4*>(&buf[st][0][4 * t]));
    }
    CP_WAIT(0);   // drain over-issued prologue groups before CTA teardown

    // ---- merge into final accumulator via L2 red.max (no partial buffer) ----
    unsigned int* gm = &g_max[which][b][4 * t];
    atomicMax(gm + 0, f2mono(mx.x));
    atomicMax(gm + 1, f2mono(mx.y));
    atomicMax(gm + 2, f2mono(mx.z));
    atomicMax(gm + 3, f2mono(mx.w));

    // ---- last-arriving CTA for this batch: decode + dot + reset ----
    __syncthreads();   // all threads' atomicMax issued before the arrival

    if (t == 0) {
        unsigned int old = arrive_acq_rel(&g_count[b]);   // release + acquire
        s_last = (old == 2u * SPLIT - 1u);
    }
    __syncthreads();
    if (!s_last) return;

    uint4 ux = *reinterpret_cast<const uint4*>(&g_max[0][b][4 * t]);
    uint4 uy = *reinterpret_cast<const uint4*>(&g_max[1][b][4 * t]);

    const float4* W4 = reinterpret_cast<const float4*>(W);
    float4 wx = W4[t];            // W[0:512]    -> x part
    float4 wy = W4[DD / 4 + t];   // W[512:1024] -> y part

    float val = wx.x * mono2f(ux.x) + wx.y * mono2f(ux.y)
              + wx.z * mono2f(ux.z) + wx.w * mono2f(ux.w)
              + wy.x * mono2f(uy.x) + wy.y * mono2f(uy.y)
              + wy.z * mono2f(uy.z) + wy.w * mono2f(uy.w);

    #pragma unroll
    for (int o = 16; o; o >>= 1) val += __shfl_down_sync(0xffffffffu, val, o);

    if ((t & 31) == 0) red[t >> 5] = val;

    // reset this batch's accumulators for the next replay
    const uint4 z = make_uint4(0, 0, 0, 0);
    *reinterpret_cast<uint4*>(&g_max[0][b][4 * t]) = z;
    *reinterpret_cast<uint4*>(&g_max[1][b][4 * t]) = z;

    __syncthreads();
    if (t == 0) {
        out[b] = red[0] + red[1] + red[2] + red[3] + bias[0];
        g_count[b] = 0;   // reset for the next graph replay
    }
}

extern "C" void kernel_launch(void* const* d_in, const int* in_sizes, int n_in,
                              void* d_out, int out_size)
{
    const float* x      = (const float*)d_in[0];
    const float* y      = (const float*)d_in[1];
    const int*   mask_x = (const int*)d_in[2];
    const int*   mask_y = (const int*)d_in[3];
    const float* W      = (const float*)d_in[4];
    const float* bias   = (const float*)d_in[5];
    float* out          = (float*)d_out;

    fused_kernel<<<dim3(SPLIT, BB, 2), 128>>>(x, y, mask_x, mask_y, W, bias, out);
}

// round 17
// speedup vs baseline: 1.5575x; 1.1275x over previous
#include <cuda_runtime.h>
#include <math_constants.h>
#include <cstdint>

// Problem constants (fixed by the reference)
#define BB 16
#define LL 2048
#define DD 512
#define SPLIT 32       // 1024 CTAs
#define NGROUPS 7      // pipeline groups -> ring = 14 rows x 2KB = 28KB
                       // (<=228KB/7 per CTA incl. driver overhead -> 7 CTAs/SM -> ONE wave)
#define RPG 2          // rows per group
#define ROWB (DD * 4)  // 2048 bytes per row

// Final max accumulators, monotone-u32 encoded. Zero == encoded(-inf).
// Zero-initialized at module load; the reducer CTA resets its batch slice
// after use, so every graph replay starts from identical state.
__device__ unsigned int g_max[2][BB][DD];
__device__ unsigned int g_count[BB];

#define CP_ASYNC16(smem_u32, gptr) \
    asm volatile("cp.async.cg.shared.global [%0], [%1], 16;\n" :: "r"(smem_u32), "l"(gptr) : "memory")
#define CP_COMMIT() asm volatile("cp.async.commit_group;\n" ::: "memory")
#define CP_WAIT(n)  asm volatile("cp.async.wait_group %0;\n" :: "n"(n) : "memory")

// Order-preserving f32 -> u32 with encoded(-inf) == 0 (inputs are finite).
__device__ __forceinline__ unsigned int f2mono(float f) {
    unsigned int u = __float_as_uint(f);
    u = (u & 0x80000000u) ? ~u : (u | 0x80000000u);
    return u - 0x007FFFFFu;
}
__device__ __forceinline__ float mono2f(unsigned int m) {
    unsigned int u = m + 0x007FFFFFu;
    u = (u & 0x80000000u) ? (u & 0x7FFFFFFFu) : ~u;
    return __uint_as_float(u);
}

__device__ __forceinline__ void fmax4(float4& a, const float4 v) {
    a.x = fmaxf(a.x, v.x); a.y = fmaxf(a.y, v.y);
    a.z = fmaxf(a.z, v.z); a.w = fmaxf(a.w, v.w);
}

// acq_rel arrival: release publishes this CTA's prior g_max atomics; acquire
// (observed by the last arriver) orders its subsequent g_max reads. Replaces
// two device-wide __threadfence() per CTA.
__device__ __forceinline__ unsigned int arrive_acq_rel(unsigned int* p) {
    unsigned int old;
    asm volatile("atom.add.acq_rel.gpu.global.u32 %0, [%1], 1;"
                 : "=r"(old) : "l"(p) : "memory");
    return old;
}

// Fused kernel: masked max, strided rows (CTA 'split' owns rows split+i*SPLIT;
// static addresses -> the 14-row cp.async prologue launches BEFORE len is known,
// hiding the mask reduction). 2 rows per commit group; wrap counters, no modulo.
// Cross-CTA combine via red.max on monotone-encoded u32; last CTA per batch
// decodes + dots W + resets state. grid=(SPLIT,B,2), block=128.
__global__ void __launch_bounds__(128, 7) fused_kernel(
    const float* __restrict__ x,
    const float* __restrict__ y,
    const int* __restrict__ mask_x,
    const int* __restrict__ mask_y,
    const float* __restrict__ W,
    const float* __restrict__ bias,
    float* __restrict__ out)
{
    __shared__ __align__(16) float buf[NGROUPS][RPG][DD];   // 28 KB ring
    __shared__ int   warp_sums[4];
    __shared__ int   s_last;
    __shared__ float red[4];

    const int split = blockIdx.x;
    const int b     = blockIdx.y;
    const int which = blockIdx.z;
    const int t     = threadIdx.x;   // 0..127

    const float* v = which ? y : x;
    const int*   m = which ? mask_y : mask_x;

    const float*   gbase = v + (size_t)b * LL * DD + 4 * t;  // this thread's 16B column
    const uint32_t smem0 = (uint32_t)__cvta_generic_to_shared(&buf[0][0][4 * t]);
    const size_t   gstep = (size_t)SPLIT * DD;               // one strided row

    // ---- prologue FIRST: groups p = strided rows (2p, 2p+1); indices <= 13 ->
    // sequence index split + 13*32 < LL, always in-bounds; rows beyond len are
    // fetched but never accumulated ----
    #pragma unroll
    for (int p = 0; p < NGROUPS; p++) {
        CP_ASYNC16(smem0 + (uint32_t)(2 * p + 0) * ROWB, gbase + (size_t)(split + (2 * p + 0) * SPLIT) * DD);
        CP_ASYNC16(smem0 + (uint32_t)(2 * p + 1) * ROWB, gbase + (size_t)(split + (2 * p + 1) * SPLIT) * DD);
        CP_COMMIT();
    }

    // ---- len[b] = L - sum(mask[b,:]) — overlapped with in-flight loads ----
    int sum = 0;
    const int4* mrow = reinterpret_cast<const int4*>(m + (size_t)b * LL);
    #pragma unroll
    for (int i = t; i < LL / 4; i += 128) {
        int4 mv = mrow[i];
        sum += mv.x + mv.y + mv.z + mv.w;
    }
    sum = __reduce_add_sync(0xffffffffu, sum);
    if ((t & 31) == 0) warp_sums[t >> 5] = sum;
    __syncthreads();
    const int len = LL - (warp_sums[0] + warp_sums[1] + warp_sums[2] + warp_sums[3]);

    // valid strided rows: split + r*SPLIT < len
    const int n       = (len > split) ? ((len - split + SPLIT - 1) / SPLIT) : 0;  // <= 64
    const int np      = (n + 1) >> 1;   // total groups to wait on
    const int np_full = n >> 1;         // groups where BOTH rows are valid

    float4 mx = make_float4(-CUDART_INF_F, -CUDART_INF_F, -CUDART_INF_F, -CUDART_INF_F);

    // ---- steady state: full pairs, branch-free consume ----
    int st = 0;                                        // ring group to consume/refill
    uint32_t sm_rd = smem0;                            // smem addr of group st (this thread)
    const float* gnext = gbase + (size_t)(split + 2 * NGROUPS * SPLIT) * DD;  // next row to issue

    for (int j = 0; j < np_full; j++) {
        CP_WAIT(NGROUPS - 1);   // 1 group/iteration -> group j has landed

        fmax4(mx, *reinterpret_cast<const float4*>(&buf[st][0][4 * t]));
        fmax4(mx, *reinterpret_cast<const float4*>(&buf[st][1][4 * t]));

        if (j + NGROUPS < np) {   // refill group st with the next row pair
            CP_ASYNC16(sm_rd,        gnext);
            CP_ASYNC16(sm_rd + ROWB, gnext + gstep);
            gnext += 2 * gstep;
        }
        CP_COMMIT();

        sm_rd += RPG * ROWB;
        if (++st == NGROUPS) { st = 0; sm_rd = smem0; }
    }
    if (np > np_full) {   // odd trailing row (first row of the last group)
        CP_WAIT(NGROUPS - 1);
        fmax4(mx, *reinterpret_cast<const float4*>(&buf[st][0][4 * t]));
    }
    CP_WAIT(0);   // drain over-issued prologue groups before CTA teardown

    // ---- merge into final accumulator via L2 red.max (no partial buffer) ----
    unsigned int* gm = &g_max[which][b][4 * t];
    atomicMax(gm + 0, f2mono(mx.x));
    atomicMax(gm + 1, f2mono(mx.y));
    atomicMax(gm + 2, f2mono(mx.z));
    atomicMax(gm + 3, f2mono(mx.w));

    // ---- last-arriving CTA for this batch: decode + dot + reset ----
    __syncthreads();   // all threads' atomicMax issued before the arrival

    if (t == 0) {
        unsigned int old = arrive_acq_rel(&g_count[b]);   // release + acquire
        s_last = (old == 2u * SPLIT - 1u);
    }
    __syncthreads();
    if (!s_last) return;

    uint4 ux = *reinterpret_cast<const uint4*>(&g_max[0][b][4 * t]);
    uint4 uy = *reinterpret_cast<const uint4*>(&g_max[1][b][4 * t]);

    const float4* W4 = reinterpret_cast<const float4*>(W);
    float4 wx = W4[t];            // W[0:512]    -> x part
    float4 wy = W4[DD / 4 + t];   // W[512:1024] -> y part

    float val = wx.x * mono2f(ux.x) + wx.y * mono2f(ux.y)
              + wx.z * mono2f(ux.z) + wx.w * mono2f(ux.w)
              + wy.x * mono2f(uy.x) + wy.y * mono2f(uy.y)
              + wy.z * mono2f(uy.z) + wy.w * mono2f(uy.w);

    #pragma unroll
    for (int o = 16; o; o >>= 1) val += __shfl_down_sync(0xffffffffu, val, o);

    if ((t & 31) == 0) red[t >> 5] = val;

    // reset this batch's accumulators for the next replay
    const uint4 z = make_uint4(0, 0, 0, 0);
    *reinterpret_cast<uint4*>(&g_max[0][b][4 * t]) = z;
    *reinterpret_cast<uint4*>(&g_max[1][b][4 * t]) = z;

    __syncthreads();
    if (t == 0) {
        out[b] = red[0] + red[1] + red[2] + red[3] + bias[0];
        g_count[b] = 0;   // reset for the next graph replay
    }
}

extern "C" void kernel_launch(void* const* d_in, const int* in_sizes, int n_in,
                              void* d_out, int out_size)
{
    const float* x      = (const float*)d_in[0];
    const float* y      = (const float*)d_in[1];
    const int*   mask_x = (const int*)d_in[2];
    const int*   mask_y = (const int*)d_in[3];
    const float* W      = (const float*)d_in[4];
    const float* bias   = (const float*)d_in[5];
    float* out          = (float*)d_out;

    fused_kernel<<<dim3(SPLIT, BB, 2), 128>>>(x, y, mask_x, mask_y, W, bias, out);
}